// round 15
// baseline (speedup 1.0000x reference)
#include <cuda_runtime.h>
#include <cuda_bf16.h>
#include <math.h>

#define BATCH 32
#define INC 3
#define OUTC 64
#define IMG 64
#define PH 32
#define NL 16
#define LEAFW 128
#define OUTW 100

typedef unsigned long long u64;

// ---------------- scratch ----------------
__device__ __nv_bfloat16 g_h1[NL * BATCH * 4 * PH * PH * 16];
__device__ __nv_bfloat16 g_w2b[NL * 4 * 25 * OUTC * 16];
__device__ __nv_bfloat16 g_w1b[NL * 5 * OUTC * 16];
__device__ __nv_bfloat16 g_xcol[BATCH * IMG * IMG * 16];
__device__ float g_feat[NL * BATCH * OUTC];
__device__ float g_mix[BATCH * NL];
__device__ float g_logits[NL * BATCH * OUTW];

__device__ __forceinline__ int icslot(int ic) {
    return ((ic & 6) << 1) | ((ic >> 3) << 1) | (ic & 1);
}
__device__ __forceinline__ int islot(int s) {
    return ((s >> 2) << 1) | ((s & 2) << 2) | (s & 1);
}

__device__ __forceinline__ void mma_bf16(float* c, unsigned a0, unsigned a1,
                                         unsigned a2, unsigned a3,
                                         unsigned b0, unsigned b1) {
    asm("mma.sync.aligned.m16n8k16.row.col.f32.bf16.bf16.f32 "
        "{%0,%1,%2,%3}, {%4,%5,%6,%7}, {%8,%9}, {%0,%1,%2,%3};"
        : "+f"(c[0]), "+f"(c[1]), "+f"(c[2]), "+f"(c[3])
        : "r"(a0), "r"(a1), "r"(a2), "r"(a3), "r"(b0), "r"(b1));
}

__device__ __forceinline__ void cp16(void* dst, const void* src, bool valid) {
    unsigned d = (unsigned)__cvta_generic_to_shared(dst);
    int sz = valid ? 16 : 0;
    asm volatile("cp.async.cg.shared.global [%0], [%1], 16, %2;"
                 :: "r"(d), "l"(__cvta_generic_to_global(src)), "r"(sz) : "memory");
}
__device__ __forceinline__ void cp_commit() {
    asm volatile("cp.async.commit_group;" ::: "memory");
}
__device__ __forceinline__ void cp_wait0() {
    asm volatile("cp.async.wait_group 0;" ::: "memory");
}

// ---------------------------------------------------------------------------
// Fused prep: w2b re-layout, w1b re-layout, xcol build, g_feat zero.
// grid 8896 x 256
// ---------------------------------------------------------------------------
__global__ void k_prep(const float* __restrict__ x,
                       const float* __restrict__ cw1,
                       const float* __restrict__ cw2) {
    int bid = blockIdx.x;
    int t = threadIdx.x;
    if (bid < 6400) {                       // w2b: 1,638,400 elems
        int e = bid * 256 + t;
        int s = e & 15;
        int oc = (e >> 4) & 63;
        int r1 = e >> 10;
        int tap = r1 % 25;
        int r2 = r1 / 25;
        int cc = r2 & 3, l = r2 >> 2;
        int ic = islot(s);
        float v = cw2[(((long)l * OUTC + oc) * OUTC + cc * 16 + ic) * 25 + tap];
        g_w2b[e] = __float2bfloat16(v);
    } else if (bid < 6720) {                // w1b: 81,920 elems
        int e = (bid - 6400) * 256 + t;
        int s = e & 15;
        int oc = (e >> 4) & 63;
        int r = e >> 10;
        int kx = r % 5, l = r / 5;
        int k = islot(s);
        float v = 0.f;
        if (k < 15) {
            int c = k / 5, ky = k % 5;
            v = cw1[(((long)l * OUTC + oc) * INC + c) * 25 + ky * 5 + kx];
        }
        g_w1b[e] = __float2bfloat16(v);
    } else if (bid < 8768) {                // xcol: 2,097,152 elems, 4/thread
        int e0 = (bid - 6720) * 1024 + t;
        #pragma unroll
        for (int j = 0; j < 4; j++) {
            int e = e0 + j * 256;
            int s = e & 15;
            int xx = (e >> 4) & 63;
            int y = (e >> 10) & 63;
            int b = e >> 16;
            int k = islot(s);
            float v = 0.f;
            if (k < 15) {
                int c = k / 5, ky = k % 5;
                int yy = y + ky - 2;
                if (yy >= 0 && yy < IMG)
                    v = x[(((long)b * INC + c) * IMG + yy) * IMG + xx];
            }
            g_xcol[e] = __float2bfloat16(v);
        }
    } else {                                // g_feat zero: 32,768
        g_feat[(bid - 8768) * 256 + t] = 0.f;
    }
}

// ---------------------------------------------------------------------------
// Routing (all 4 depths) + mixture for this batch. grid 32, block 256.
// ---------------------------------------------------------------------------
__global__ void k_route(const float* __restrict__ x, const float* __restrict__ nw,
                        const float* __restrict__ nb) {
    extern __shared__ float rsm[];
    float* slab = rsm;                 // 3*68*68
    float* swf = rsm + 13872;          // 4*75
    __shared__ float red[8][4];
    __shared__ float fsc[4];

    int b = blockIdx.x, t = threadIdx.x;
    for (int idx = t; idx < 3 * 68 * 68; idx += 256) {
        int c = idx / 4624;
        int rem = idx % 4624;
        int yy = rem / 68, xx = rem % 68;
        int gy = yy - 2, gx = xx - 2;
        float v = 0.f;
        if (gy >= 0 && gy < IMG && gx >= 0 && gx < IMG)
            v = x[(((long)b * INC + c) * IMG + gy) * IMG + gx];
        slab[idx] = v;
    }
    for (int idx = t; idx < 4 * 75; idx += 256) {
        int d = idx / 75, j = idx % 75;
        swf[idx] = nw[((2 << d) - 2) * 75 + j];
    }
    __syncthreads();

    float sc[4] = {-1e30f, -1e30f, -1e30f, -1e30f};
    for (int p = t; p < IMG * IMG; p += 256) {
        int y = p >> 6, xx = p & 63;
        float a0 = 0.f, a1 = 0.f, a2 = 0.f, a3 = 0.f;
        #pragma unroll
        for (int c = 0; c < INC; c++)
            #pragma unroll
            for (int ky = 0; ky < 5; ky++)
                #pragma unroll
                for (int kx = 0; kx < 5; kx++) {
                    float v = slab[c * 4624 + (y + ky) * 68 + xx + kx];
                    int w = c * 25 + ky * 5 + kx;
                    a0 = fmaf(v, swf[w], a0);
                    a1 = fmaf(v, swf[75 + w], a1);
                    a2 = fmaf(v, swf[150 + w], a2);
                    a3 = fmaf(v, swf[225 + w], a3);
                }
        sc[0] = fmaxf(sc[0], a0); sc[1] = fmaxf(sc[1], a1);
        sc[2] = fmaxf(sc[2], a2); sc[3] = fmaxf(sc[3], a3);
    }
    #pragma unroll
    for (int d = 0; d < 4; d++)
        #pragma unroll
        for (int off = 16; off > 0; off >>= 1)
            sc[d] = fmaxf(sc[d], __shfl_xor_sync(0xffffffffu, sc[d], off));
    if ((t & 31) == 0)
        #pragma unroll
        for (int d = 0; d < 4; d++) red[t >> 5][d] = sc[d];
    __syncthreads();
    if (t < 4) {
        float m = red[0][t];
        #pragma unroll
        for (int w = 1; w < 8; w++) m = fmaxf(m, red[w][t]);
        fsc[t] = m;
    }
    __syncthreads();
    if (t < NL) {
        int l = t;
        float m = 1.f;
        #pragma unroll
        for (int d = 0; d < 4; d++) {
            int j = l >> (4 - d);
            int bit = (l >> (3 - d)) & 1;
            float z = fsc[d] + nb[(1 << d) - 1 + j];
            float be = 1.f / (1.f + expf(-z));
            m *= bit ? be : (1.f - be);
        }
        g_mix[b * NL + l] = m;
    }
}

// ---------------------------------------------------------------------------
// conv1 via bf16 mma, warp tile M64(all oc) x N64 (2 rows x 32 cols).
// grid (lb=512, q=0..7); block 256 = 8 warps (rp = wid>>1, ch = wid&1).
// ---------------------------------------------------------------------------
__global__ void __launch_bounds__(256) k_conv1m() {
    __shared__ __nv_bfloat16 sxc[8 * 68 * 16];   // 17408 B
    __shared__ __nv_bfloat16 sw1[5 * 64 * 16];   // 10240 B

    int lb = blockIdx.x;
    int l = lb >> 5, b = lb & 31;
    int q = blockIdx.y;
    int t = threadIdx.x;
    int wid = t >> 5, lane = t & 31;
    int rp = wid >> 1, ch = wid & 1;
    int g = lane >> 2, c4 = lane & 3;

    const __nv_bfloat16* xb = g_xcol + (long)b * (IMG * IMG * 16);
    for (int idx = t; idx < 1088; idx += 256) {
        int j = idx & 1, pos = idx >> 1;
        int col = pos % 68, row = pos / 68;
        int gx = col - 2;
        uint4 v = make_uint4(0, 0, 0, 0);
        if (gx >= 0 && gx < IMG)
            v = *(const uint4*)(xb + ((q * 8 + row) * IMG + gx) * 16 + j * 8);
        *(uint4*)(sxc + pos * 16 + j * 8) = v;
    }
    const __nv_bfloat16* wsrc = g_w1b + (long)l * 5120;
    for (int idx = t; idx < 640; idx += 256)
        *(uint4*)(sw1 + idx * 8) = *(const uint4*)(wsrc + idx * 8);
    __syncthreads();

    float acc[4][8][4];
    #pragma unroll
    for (int i = 0; i < 4; i++)
        #pragma unroll
        for (int j = 0; j < 8; j++)
            #pragma unroll
            for (int k = 0; k < 4; k++) acc[i][j][k] = 0.f;

    #pragma unroll
    for (int kx = 0; kx < 5; kx++) {
        const char* wtap = (const char*)sw1 + kx * 2048 + 8 * c4;
        u64 aw[4][2];
        #pragma unroll
        for (int mt = 0; mt < 4; mt++) {
            aw[mt][0] = *(const u64*)(wtap + (mt * 16 + g) * 32);
            aw[mt][1] = *(const u64*)(wtap + (mt * 16 + g + 8) * 32);
        }
        const char* bbase = (const char*)sxc +
            ((rp * 2) * 68 + ch * 32 + g + kx) * 32 + 8 * c4;
        #pragma unroll
        for (int nt = 0; nt < 8; nt++) {
            u64 bb = *(const u64*)(bbase + ((nt >> 2) * 68 + (nt & 3) * 8) * 32);
            unsigned b0 = (unsigned)bb, b1 = (unsigned)(bb >> 32);
            #pragma unroll
            for (int mt = 0; mt < 4; mt++)
                mma_bf16(acc[mt][nt], (unsigned)aw[mt][0], (unsigned)aw[mt][1],
                         (unsigned)(aw[mt][0] >> 32), (unsigned)(aw[mt][1] >> 32),
                         b0, b1);
        }
    }

    // 2x2 pool + relu + store bf16 interleaved. pooled row = q*4+rp.
    int prow = q * 4 + rp;
    __nv_bfloat16* hout = g_h1 + (long)lb * (4 * PH * PH * 16);
    #pragma unroll
    for (int mt = 0; mt < 4; mt++) {
        #pragma unroll
        for (int xg = 0; xg < 4; xg++) {
            float* c0 = acc[mt][xg];        // r=0
            float* c1 = acc[mt][4 + xg];    // r=1
            float plo = fmaxf(fmaxf(c0[0], c0[1]), fmaxf(c1[0], c1[1]));
            float phi = fmaxf(fmaxf(c0[2], c0[3]), fmaxf(c1[2], c1[3]));
            plo = fmaxf(plo, 0.f);
            phi = fmaxf(phi, 0.f);
            int pcol = ch * 16 + xg * 4 + c4;
            long base = ((long)mt * (PH * PH) + prow * PH + pcol) * 16;
            hout[base + icslot(g)] = __float2bfloat16(plo);
            hout[base + icslot(g + 8)] = __float2bfloat16(phi);
        }
    }
}

// ---------------------------------------------------------------------------
// conv2 via bf16 mma, warp tile M64 x N64, double-buffered cp.async.
// grid (lb=512, q 0..1); block 256 = 8 warps (wn = wid -> 2 spatial rows).
// smem: 2 x (51200 + 23040) = 148480 B
// ---------------------------------------------------------------------------
__global__ void __launch_bounds__(256) k_conv2() {
    extern __shared__ __align__(16) char dsm[];
    char* wb[2] = {dsm, dsm + 51200};
    char* ib[2] = {dsm + 102400, dsm + 102400 + 23040};

    int lb = blockIdx.x;
    int l = lb >> 5;
    int q = blockIdx.y;
    int t = threadIdx.x;
    int wn = t >> 5, lane = t & 31;
    int g = lane >> 2, c4 = lane & 3;

    const __nv_bfloat16* h1base = g_h1 + (long)lb * (4 * PH * PH * 16);
    const __nv_bfloat16* w2base = g_w2b + (long)l * (4 * 25 * OUTC * 16);

    auto stage = [&](int cc, int buf) {
        const char* wsrc = (const char*)(w2base + (long)cc * 25 * OUTC * 16);
        char* wdst = wb[buf];
        for (int idx = t; idx < 3200; idx += 256)
            cp16(wdst + idx * 16, wsrc + idx * 16, true);
        const __nv_bfloat16* hplane = h1base + (long)cc * (PH * PH * 16);
        char* idst = ib[buf];
        for (int idx = t; idx < 1440; idx += 256) {
            int j = idx & 1, pos = idx >> 1;
            int xx = pos % 36, yy = pos / 36;
            int gy = q * 16 + yy - 2, gx = xx - 2;
            bool val = (gy >= 0 && gy < PH && gx >= 0 && gx < PH);
            const char* src = (const char*)(hplane +
                               ((val ? (gy * PH + gx) : 0) * 16)) + j * 16;
            cp16(idst + pos * 32 + j * 16, src, val);
        }
        cp_commit();
    };

    float acc[4][8][4];
    #pragma unroll
    for (int i = 0; i < 4; i++)
        #pragma unroll
        for (int j = 0; j < 8; j++)
            #pragma unroll
            for (int k = 0; k < 4; k++) acc[i][j][k] = 0.f;

    stage(0, 0);

    #pragma unroll 1
    for (int cc = 0; cc < 4; cc++) {
        cp_wait0();
        __syncthreads();
        if (cc < 3) stage(cc + 1, (cc + 1) & 1);

        const char* swb = wb[cc & 1];
        const char* sib = ib[cc & 1];

        #pragma unroll 1
        for (int ky = 0; ky < 5; ky++) {
            #pragma unroll 1
            for (int kx = 0; kx < 5; kx++) {
                int tap = ky * 5 + kx;
                const char* wtap = swb + tap * 2048 + 8 * c4;
                u64 aw[4][2];
                #pragma unroll
                for (int mt = 0; mt < 4; mt++) {
                    aw[mt][0] = *(const u64*)(wtap + (mt * 16 + g) * 32);
                    aw[mt][1] = *(const u64*)(wtap + (mt * 16 + g + 8) * 32);
                }
                const char* bbase = sib +
                    ((wn * 2 + ky) * 36 + g + kx) * 32 + 8 * c4;
                #pragma unroll
                for (int nt = 0; nt < 8; nt++) {
                    u64 bb = *(const u64*)(bbase +
                               ((nt >> 2) * 36 + (nt & 3) * 8) * 32);
                    unsigned b0 = (unsigned)bb, b1 = (unsigned)(bb >> 32);
                    #pragma unroll
                    for (int mt = 0; mt < 4; mt++)
                        mma_bf16(acc[mt][nt],
                                 (unsigned)aw[mt][0], (unsigned)aw[mt][1],
                                 (unsigned)(aw[mt][0] >> 32),
                                 (unsigned)(aw[mt][1] >> 32), b0, b1);
                }
            }
        }
        __syncthreads();
    }

    // relu + spatial max -> atomicMax (g_feat zeroed in k_prep)
    #pragma unroll
    for (int mt = 0; mt < 4; mt++) {
        float mlo = 0.f, mhi = 0.f;
        #pragma unroll
        for (int nt = 0; nt < 8; nt++) {
            mlo = fmaxf(mlo, fmaxf(acc[mt][nt][0], acc[mt][nt][1]));
            mhi = fmaxf(mhi, fmaxf(acc[mt][nt][2], acc[mt][nt][3]));
        }
        mlo = fmaxf(mlo, __shfl_xor_sync(0xffffffffu, mlo, 1));
        mlo = fmaxf(mlo, __shfl_xor_sync(0xffffffffu, mlo, 2));
        mhi = fmaxf(mhi, __shfl_xor_sync(0xffffffffu, mhi, 1));
        mhi = fmaxf(mhi, __shfl_xor_sync(0xffffffffu, mhi, 2));
        if (c4 == 0) {
            int base = lb * OUTC + mt * 16 + g;
            atomicMax((int*)&g_feat[base], __float_as_int(mlo));
            atomicMax((int*)&g_feat[base + 8], __float_as_int(mhi));
        }
    }
}

// ---------------------------------------------------------------------------
// Per-leaf MLP
// ---------------------------------------------------------------------------
__global__ void k_mlp(const float* __restrict__ w1, const float* __restrict__ b1,
                      const float* __restrict__ w2, const float* __restrict__ b2) {
    int lb = blockIdx.x;
    int l = lb >> 5, b = lb & 31;
    int t = threadIdx.x;
    __shared__ float sfeat[OUTC];
    __shared__ float shid[LEAFW];
    if (t < OUTC) sfeat[t] = g_feat[((long)l * BATCH + b) * OUTC + t];
    __syncthreads();
    float hsum = b1[l * LEAFW + t];
    #pragma unroll 8
    for (int k = 0; k < OUTC; k++)
        hsum = fmaf(sfeat[k], w1[((long)l * OUTC + k) * LEAFW + t], hsum);
    shid[t] = hsum;
    __syncthreads();
    if (t < OUTW) {
        float o = b2[l * OUTW + t];
        #pragma unroll 8
        for (int j = 0; j < LEAFW; j++)
            o = fmaf(shid[j], w2[((long)l * LEAFW + j) * OUTW + t], o);
        g_logits[((long)l * BATCH + b) * OUTW + t] = o;
    }
}

__global__ void k_final(float* __restrict__ out) {
    int b = blockIdx.x;
    int t = threadIdx.x;
    if (t < OUTW) {
        float s = 0.f;
        #pragma unroll
        for (int l = 0; l < NL; l++)
            s = fmaf(g_logits[((long)l * BATCH + b) * OUTW + t], g_mix[b * NL + l], s);
        out[b * OUTW + t] = s;
    }
}

// ---------------------------------------------------------------------------
extern "C" void kernel_launch(void* const* d_in, const int* in_sizes, int n_in,
                              void* d_out, int out_size) {
    const float* x   = (const float*)d_in[0];
    const float* nw  = (const float*)d_in[1];
    const float* nb  = (const float*)d_in[2];
    const float* cw1 = (const float*)d_in[3];
    const float* cw2 = (const float*)d_in[4];
    const float* w1  = (const float*)d_in[5];
    const float* b1  = (const float*)d_in[6];
    const float* w2  = (const float*)d_in[7];
    const float* b2  = (const float*)d_in[8];
    float* out = (float*)d_out;

    cudaFuncSetAttribute(k_conv2, cudaFuncAttributeMaxDynamicSharedMemorySize, 148480);
    cudaFuncSetAttribute(k_route, cudaFuncAttributeMaxDynamicSharedMemorySize, 56688);

    k_prep<<<8896, 256>>>(x, cw1, cw2);
    k_route<<<32, 256, (13872 + 300) * 4>>>(x, nw, nb);
    k_conv1m<<<dim3(NL * BATCH, 8), 256>>>();
    k_conv2<<<dim3(NL * BATCH, 2), 256, 148480>>>();
    k_mlp<<<NL * BATCH, 128>>>(w1, b1, w2, b2);
    k_final<<<BATCH, 128>>>(out);
}

// round 16
// speedup vs baseline: 1.0097x; 1.0097x over previous
#include <cuda_runtime.h>
#include <cuda_bf16.h>
#include <math.h>

#define BATCH 32
#define INC 3
#define OUTC 64
#define IMG 64
#define PH 32
#define NL 16
#define LEAFW 128
#define OUTW 100

typedef unsigned long long u64;

// ---------------- scratch ----------------
__device__ __nv_bfloat16 g_h1[NL * BATCH * 4 * PH * PH * 16];
__device__ __nv_bfloat16 g_w2b[NL * 4 * 25 * OUTC * 16];
__device__ __nv_bfloat16 g_w1b[NL * 5 * OUTC * 16];
__device__ __nv_bfloat16 g_xcol[BATCH * IMG * IMG * 16];
__device__ float g_feat[NL * BATCH * OUTC];
__device__ float g_mix[BATCH * NL];
__device__ float g_logits[NL * BATCH * OUTW];

__device__ __forceinline__ int icslot(int ic) {
    return ((ic & 6) << 1) | ((ic >> 3) << 1) | (ic & 1);
}
__device__ __forceinline__ int islot(int s) {
    return ((s >> 2) << 1) | ((s & 2) << 2) | (s & 1);
}

__device__ __forceinline__ void mma_bf16(float* c, unsigned a0, unsigned a1,
                                         unsigned a2, unsigned a3,
                                         unsigned b0, unsigned b1) {
    asm("mma.sync.aligned.m16n8k16.row.col.f32.bf16.bf16.f32 "
        "{%0,%1,%2,%3}, {%4,%5,%6,%7}, {%8,%9}, {%0,%1,%2,%3};"
        : "+f"(c[0]), "+f"(c[1]), "+f"(c[2]), "+f"(c[3])
        : "r"(a0), "r"(a1), "r"(a2), "r"(a3), "r"(b0), "r"(b1));
}

__device__ __forceinline__ void cp16(void* dst, const void* src, bool valid) {
    unsigned d = (unsigned)__cvta_generic_to_shared(dst);
    int sz = valid ? 16 : 0;
    asm volatile("cp.async.cg.shared.global [%0], [%1], 16, %2;"
                 :: "r"(d), "l"(__cvta_generic_to_global(src)), "r"(sz) : "memory");
}
__device__ __forceinline__ void cp_commit() {
    asm volatile("cp.async.commit_group;" ::: "memory");
}
__device__ __forceinline__ void cp_wait0() {
    asm volatile("cp.async.wait_group 0;" ::: "memory");
}

// ---------------------------------------------------------------------------
// Fused prep: w2b re-layout, w1b re-layout, xcol build, g_feat zero.
// grid 8896 x 256
// ---------------------------------------------------------------------------
__global__ void k_prep(const float* __restrict__ x,
                       const float* __restrict__ cw1,
                       const float* __restrict__ cw2) {
    int bid = blockIdx.x;
    int t = threadIdx.x;
    if (bid < 6400) {                       // w2b: 1,638,400 elems
        int e = bid * 256 + t;
        int s = e & 15;
        int oc = (e >> 4) & 63;
        int r1 = e >> 10;
        int tap = r1 % 25;
        int r2 = r1 / 25;
        int cc = r2 & 3, l = r2 >> 2;
        int ic = islot(s);
        float v = cw2[(((long)l * OUTC + oc) * OUTC + cc * 16 + ic) * 25 + tap];
        g_w2b[e] = __float2bfloat16(v);
    } else if (bid < 6720) {                // w1b: 81,920 elems
        int e = (bid - 6400) * 256 + t;
        int s = e & 15;
        int oc = (e >> 4) & 63;
        int r = e >> 10;
        int kx = r % 5, l = r / 5;
        int k = islot(s);
        float v = 0.f;
        if (k < 15) {
            int c = k / 5, ky = k % 5;
            v = cw1[(((long)l * OUTC + oc) * INC + c) * 25 + ky * 5 + kx];
        }
        g_w1b[e] = __float2bfloat16(v);
    } else if (bid < 8768) {                // xcol: 2,097,152 elems, 4/thread
        int e0 = (bid - 6720) * 1024 + t;
        #pragma unroll
        for (int j = 0; j < 4; j++) {
            int e = e0 + j * 256;
            int s = e & 15;
            int xx = (e >> 4) & 63;
            int y = (e >> 10) & 63;
            int b = e >> 16;
            int k = islot(s);
            float v = 0.f;
            if (k < 15) {
                int c = k / 5, ky = k % 5;
                int yy = y + ky - 2;
                if (yy >= 0 && yy < IMG)
                    v = x[(((long)b * INC + c) * IMG + yy) * IMG + xx];
            }
            g_xcol[e] = __float2bfloat16(v);
        }
    } else {                                // g_feat zero: 32,768
        g_feat[(bid - 8768) * 256 + t] = 0.f;
    }
}

// ---------------------------------------------------------------------------
// Routing (all 4 depths) + mixture for this batch. grid 32, block 256.
// ---------------------------------------------------------------------------
__global__ void k_route(const float* __restrict__ x, const float* __restrict__ nw,
                        const float* __restrict__ nb) {
    extern __shared__ float rsm[];
    float* slab = rsm;                 // 3*68*68
    float* swf = rsm + 13872;          // 4*75
    __shared__ float red[8][4];
    __shared__ float fsc[4];

    int b = blockIdx.x, t = threadIdx.x;
    for (int idx = t; idx < 3 * 68 * 68; idx += 256) {
        int c = idx / 4624;
        int rem = idx % 4624;
        int yy = rem / 68, xx = rem % 68;
        int gy = yy - 2, gx = xx - 2;
        float v = 0.f;
        if (gy >= 0 && gy < IMG && gx >= 0 && gx < IMG)
            v = x[(((long)b * INC + c) * IMG + gy) * IMG + gx];
        slab[idx] = v;
    }
    for (int idx = t; idx < 4 * 75; idx += 256) {
        int d = idx / 75, j = idx % 75;
        swf[idx] = nw[((2 << d) - 2) * 75 + j];
    }
    __syncthreads();

    float sc[4] = {-1e30f, -1e30f, -1e30f, -1e30f};
    for (int p = t; p < IMG * IMG; p += 256) {
        int y = p >> 6, xx = p & 63;
        float a0 = 0.f, a1 = 0.f, a2 = 0.f, a3 = 0.f;
        #pragma unroll
        for (int c = 0; c < INC; c++)
            #pragma unroll
            for (int ky = 0; ky < 5; ky++)
                #pragma unroll
                for (int kx = 0; kx < 5; kx++) {
                    float v = slab[c * 4624 + (y + ky) * 68 + xx + kx];
                    int w = c * 25 + ky * 5 + kx;
                    a0 = fmaf(v, swf[w], a0);
                    a1 = fmaf(v, swf[75 + w], a1);
                    a2 = fmaf(v, swf[150 + w], a2);
                    a3 = fmaf(v, swf[225 + w], a3);
                }
        sc[0] = fmaxf(sc[0], a0); sc[1] = fmaxf(sc[1], a1);
        sc[2] = fmaxf(sc[2], a2); sc[3] = fmaxf(sc[3], a3);
    }
    #pragma unroll
    for (int d = 0; d < 4; d++)
        #pragma unroll
        for (int off = 16; off > 0; off >>= 1)
            sc[d] = fmaxf(sc[d], __shfl_xor_sync(0xffffffffu, sc[d], off));
    if ((t & 31) == 0)
        #pragma unroll
        for (int d = 0; d < 4; d++) red[t >> 5][d] = sc[d];
    __syncthreads();
    if (t < 4) {
        float m = red[0][t];
        #pragma unroll
        for (int w = 1; w < 8; w++) m = fmaxf(m, red[w][t]);
        fsc[t] = m;
    }
    __syncthreads();
    if (t < NL) {
        int l = t;
        float m = 1.f;
        #pragma unroll
        for (int d = 0; d < 4; d++) {
            int j = l >> (4 - d);
            int bit = (l >> (3 - d)) & 1;
            float z = fsc[d] + nb[(1 << d) - 1 + j];
            float be = 1.f / (1.f + expf(-z));
            m *= bit ? be : (1.f - be);
        }
        g_mix[b * NL + l] = m;
    }
}

// ---------------------------------------------------------------------------
// conv1 via bf16 mma, warp tile M64(all oc) x N64 (2 rows x 32 cols).
// grid (lb=512, q=0..7); block 256 = 8 warps (rp = wid>>1, ch = wid&1).
// ---------------------------------------------------------------------------
__global__ void __launch_bounds__(256) k_conv1m() {
    __shared__ __nv_bfloat16 sxc[8 * 68 * 16];   // 17408 B
    __shared__ __nv_bfloat16 sw1[5 * 64 * 16];   // 10240 B

    int lb = blockIdx.x;
    int l = lb >> 5, b = lb & 31;
    int q = blockIdx.y;
    int t = threadIdx.x;
    int wid = t >> 5, lane = t & 31;
    int rp = wid >> 1, ch = wid & 1;
    int g = lane >> 2, c4 = lane & 3;

    const __nv_bfloat16* xb = g_xcol + (long)b * (IMG * IMG * 16);
    for (int idx = t; idx < 1088; idx += 256) {
        int j = idx & 1, pos = idx >> 1;
        int col = pos % 68, row = pos / 68;
        int gx = col - 2;
        uint4 v = make_uint4(0, 0, 0, 0);
        if (gx >= 0 && gx < IMG)
            v = *(const uint4*)(xb + ((q * 8 + row) * IMG + gx) * 16 + j * 8);
        *(uint4*)(sxc + pos * 16 + j * 8) = v;
    }
    const __nv_bfloat16* wsrc = g_w1b + (long)l * 5120;
    for (int idx = t; idx < 640; idx += 256)
        *(uint4*)(sw1 + idx * 8) = *(const uint4*)(wsrc + idx * 8);
    __syncthreads();

    float acc[4][8][4];
    #pragma unroll
    for (int i = 0; i < 4; i++)
        #pragma unroll
        for (int j = 0; j < 8; j++)
            #pragma unroll
            for (int k = 0; k < 4; k++) acc[i][j][k] = 0.f;

    #pragma unroll
    for (int kx = 0; kx < 5; kx++) {
        const char* wtap = (const char*)sw1 + kx * 2048 + 8 * c4;
        u64 aw[4][2];
        #pragma unroll
        for (int mt = 0; mt < 4; mt++) {
            aw[mt][0] = *(const u64*)(wtap + (mt * 16 + g) * 32);
            aw[mt][1] = *(const u64*)(wtap + (mt * 16 + g + 8) * 32);
        }
        const char* bbase = (const char*)sxc +
            ((rp * 2) * 68 + ch * 32 + g + kx) * 32 + 8 * c4;
        #pragma unroll
        for (int nt = 0; nt < 8; nt++) {
            u64 bb = *(const u64*)(bbase + ((nt >> 2) * 68 + (nt & 3) * 8) * 32);
            unsigned b0 = (unsigned)bb, b1 = (unsigned)(bb >> 32);
            #pragma unroll
            for (int mt = 0; mt < 4; mt++)
                mma_bf16(acc[mt][nt], (unsigned)aw[mt][0], (unsigned)aw[mt][1],
                         (unsigned)(aw[mt][0] >> 32), (unsigned)(aw[mt][1] >> 32),
                         b0, b1);
        }
    }

    // 2x2 pool + relu + store bf16 interleaved. pooled row = q*4+rp.
    int prow = q * 4 + rp;
    __nv_bfloat16* hout = g_h1 + (long)lb * (4 * PH * PH * 16);
    #pragma unroll
    for (int mt = 0; mt < 4; mt++) {
        #pragma unroll
        for (int xg = 0; xg < 4; xg++) {
            float* c0 = acc[mt][xg];        // r=0
            float* c1 = acc[mt][4 + xg];    // r=1
            float plo = fmaxf(fmaxf(c0[0], c0[1]), fmaxf(c1[0], c1[1]));
            float phi = fmaxf(fmaxf(c0[2], c0[3]), fmaxf(c1[2], c1[3]));
            plo = fmaxf(plo, 0.f);
            phi = fmaxf(phi, 0.f);
            int pcol = ch * 16 + xg * 4 + c4;
            long base = ((long)mt * (PH * PH) + prow * PH + pcol) * 16;
            hout[base + icslot(g)] = __float2bfloat16(plo);
            hout[base + icslot(g + 8)] = __float2bfloat16(phi);
        }
    }
}

// ---------------------------------------------------------------------------
// conv2 via bf16 mma, warp tile M64 x N64, double-buffered cp.async.
// grid (lb=512, q 0..1); block 256 = 8 warps (wn = wid -> 2 spatial rows).
// smem: 2 x (51200 + 23040) = 148480 B
// ---------------------------------------------------------------------------
__global__ void __launch_bounds__(256) k_conv2() {
    extern __shared__ __align__(16) char dsm[];
    char* wb[2] = {dsm, dsm + 51200};
    char* ib[2] = {dsm + 102400, dsm + 102400 + 23040};

    int lb = blockIdx.x;
    int l = lb >> 5;
    int q = blockIdx.y;
    int t = threadIdx.x;
    int wn = t >> 5, lane = t & 31;
    int g = lane >> 2, c4 = lane & 3;

    const __nv_bfloat16* h1base = g_h1 + (long)lb * (4 * PH * PH * 16);
    const __nv_bfloat16* w2base = g_w2b + (long)l * (4 * 25 * OUTC * 16);

    auto stage = [&](int cc, int buf) {
        const char* wsrc = (const char*)(w2base + (long)cc * 25 * OUTC * 16);
        char* wdst = wb[buf];
        for (int idx = t; idx < 3200; idx += 256)
            cp16(wdst + idx * 16, wsrc + idx * 16, true);
        const __nv_bfloat16* hplane = h1base + (long)cc * (PH * PH * 16);
        char* idst = ib[buf];
        for (int idx = t; idx < 1440; idx += 256) {
            int j = idx & 1, pos = idx >> 1;
            int xx = pos % 36, yy = pos / 36;
            int gy = q * 16 + yy - 2, gx = xx - 2;
            bool val = (gy >= 0 && gy < PH && gx >= 0 && gx < PH);
            const char* src = (const char*)(hplane +
                               ((val ? (gy * PH + gx) : 0) * 16)) + j * 16;
            cp16(idst + pos * 32 + j * 16, src, val);
        }
        cp_commit();
    };

    float acc[4][8][4];
    #pragma unroll
    for (int i = 0; i < 4; i++)
        #pragma unroll
        for (int j = 0; j < 8; j++)
            #pragma unroll
            for (int k = 0; k < 4; k++) acc[i][j][k] = 0.f;

    stage(0, 0);

    #pragma unroll 1
    for (int cc = 0; cc < 4; cc++) {
        cp_wait0();
        __syncthreads();
        if (cc < 3) stage(cc + 1, (cc + 1) & 1);

        const char* swb = wb[cc & 1];
        const char* sib = ib[cc & 1];

        #pragma unroll 1
        for (int ky = 0; ky < 5; ky++) {
            #pragma unroll 1
            for (int kx = 0; kx < 5; kx++) {
                int tap = ky * 5 + kx;
                const char* wtap = swb + tap * 2048 + 8 * c4;
                u64 aw[4][2];
                #pragma unroll
                for (int mt = 0; mt < 4; mt++) {
                    aw[mt][0] = *(const u64*)(wtap + (mt * 16 + g) * 32);
                    aw[mt][1] = *(const u64*)(wtap + (mt * 16 + g + 8) * 32);
                }
                const char* bbase = sib +
                    ((wn * 2 + ky) * 36 + g + kx) * 32 + 8 * c4;
                #pragma unroll
                for (int nt = 0; nt < 8; nt++) {
                    u64 bb = *(const u64*)(bbase +
                               ((nt >> 2) * 36 + (nt & 3) * 8) * 32);
                    unsigned b0 = (unsigned)bb, b1 = (unsigned)(bb >> 32);
                    #pragma unroll
                    for (int mt = 0; mt < 4; mt++)
                        mma_bf16(acc[mt][nt],
                                 (unsigned)aw[mt][0], (unsigned)aw[mt][1],
                                 (unsigned)(aw[mt][0] >> 32),
                                 (unsigned)(aw[mt][1] >> 32), b0, b1);
                }
            }
        }
        __syncthreads();
    }

    // relu + spatial max -> atomicMax (g_feat zeroed in k_prep)
    #pragma unroll
    for (int mt = 0; mt < 4; mt++) {
        float mlo = 0.f, mhi = 0.f;
        #pragma unroll
        for (int nt = 0; nt < 8; nt++) {
            mlo = fmaxf(mlo, fmaxf(acc[mt][nt][0], acc[mt][nt][1]));
            mhi = fmaxf(mhi, fmaxf(acc[mt][nt][2], acc[mt][nt][3]));
        }
        mlo = fmaxf(mlo, __shfl_xor_sync(0xffffffffu, mlo, 1));
        mlo = fmaxf(mlo, __shfl_xor_sync(0xffffffffu, mlo, 2));
        mhi = fmaxf(mhi, __shfl_xor_sync(0xffffffffu, mhi, 1));
        mhi = fmaxf(mhi, __shfl_xor_sync(0xffffffffu, mhi, 2));
        if (c4 == 0) {
            int base = lb * OUTC + mt * 16 + g;
            atomicMax((int*)&g_feat[base], __float_as_int(mlo));
            atomicMax((int*)&g_feat[base + 8], __float_as_int(mhi));
        }
    }
}

// ---------------------------------------------------------------------------
// Per-leaf MLP
// ---------------------------------------------------------------------------
__global__ void k_mlp(const float* __restrict__ w1, const float* __restrict__ b1,
                      const float* __restrict__ w2, const float* __restrict__ b2) {
    int lb = blockIdx.x;
    int l = lb >> 5, b = lb & 31;
    int t = threadIdx.x;
    __shared__ float sfeat[OUTC];
    __shared__ float shid[LEAFW];
    if (t < OUTC) sfeat[t] = g_feat[((long)l * BATCH + b) * OUTC + t];
    __syncthreads();
    float hsum = b1[l * LEAFW + t];
    #pragma unroll 8
    for (int k = 0; k < OUTC; k++)
        hsum = fmaf(sfeat[k], w1[((long)l * OUTC + k) * LEAFW + t], hsum);
    shid[t] = hsum;
    __syncthreads();
    if (t < OUTW) {
        float o = b2[l * OUTW + t];
        #pragma unroll 8
        for (int j = 0; j < LEAFW; j++)
            o = fmaf(shid[j], w2[((long)l * LEAFW + j) * OUTW + t], o);
        g_logits[((long)l * BATCH + b) * OUTW + t] = o;
    }
}

__global__ void k_final(float* __restrict__ out) {
    int b = blockIdx.x;
    int t = threadIdx.x;
    if (t < OUTW) {
        float s = 0.f;
        #pragma unroll
        for (int l = 0; l < NL; l++)
            s = fmaf(g_logits[((long)l * BATCH + b) * OUTW + t], g_mix[b * NL + l], s);
        out[b * OUTW + t] = s;
    }
}

// ---------------------------------------------------------------------------
extern "C" void kernel_launch(void* const* d_in, const int* in_sizes, int n_in,
                              void* d_out, int out_size) {
    const float* x   = (const float*)d_in[0];
    const float* nw  = (const float*)d_in[1];
    const float* nb  = (const float*)d_in[2];
    const float* cw1 = (const float*)d_in[3];
    const float* cw2 = (const float*)d_in[4];
    const float* w1  = (const float*)d_in[5];
    const float* b1  = (const float*)d_in[6];
    const float* w2  = (const float*)d_in[7];
    const float* b2  = (const float*)d_in[8];
    float* out = (float*)d_out;

    cudaFuncSetAttribute(k_conv2, cudaFuncAttributeMaxDynamicSharedMemorySize, 148480);
    cudaFuncSetAttribute(k_route, cudaFuncAttributeMaxDynamicSharedMemorySize, 56688);

    k_prep<<<8896, 256>>>(x, cw1, cw2);
    k_route<<<32, 256, (13872 + 300) * 4>>>(x, nw, nb);
    k_conv1m<<<dim3(NL * BATCH, 8), 256>>>();
    k_conv2<<<dim3(NL * BATCH, 2), 256, 148480>>>();
    k_mlp<<<NL * BATCH, 128>>>(w1, b1, w2, b2);
    k_final<<<BATCH, 128>>>(out);
}